// round 9
// baseline (speedup 1.0000x reference)
#include <cuda_runtime.h>
#include <math.h>

#define NA 48
#define NS 4
#define NSHFR 16
#define NSHFA 4
#define NSHFZ 8
#define RAD_FEAT (NS * NSHFR)                     // 64
#define ANG_SUB (NSHFA * NSHFZ)                   // 32
#define NPAIRS_SP (NS * (NS + 1) / 2)             // 10
#define ANG_FEAT (NPAIRS_SP * ANG_SUB)            // 320
#define AEV_LEN (RAD_FEAT + ANG_FEAT)             // 384
#define RCR_F 5.2f
#define RCA_F 3.5f
#define PI_F 3.14159265358979323846f
#define NTHR 256
#define GWARPS 4          // warps per group
#define CHUNK 128         // pairs per chunk per group

// group barrier: 128 threads, barrier id 1+g (id 0 reserved for full-CTA sync)
#define GBAR(g) asm volatile("bar.sync %0, %1;" :: "r"((g) + 1), "r"(128) : "memory")

__device__ __forceinline__ int triu_idx(int a, int b) {
    int lo = min(a, b), hi = max(a, b);
    return lo * NS - (lo * (lo - 1)) / 2 + (hi - lo);
}

__device__ __forceinline__ float pow_zeta(float x, float zeta, bool z32) {
    if (z32) {
        float y = x * x;  // ^2
        y = y * y;        // ^4
        y = y * y;        // ^8
        y = y * y;        // ^16
        return y * y;     // ^32
    }
    return __powf(x, zeta);
}

__global__ __launch_bounds__(NTHR, 6)
void aev_kernel(const float* __restrict__ coords,   // (M, A, 3)
                const float* __restrict__ gEtaR,
                const float* __restrict__ gShfR,    // (16,)
                const float* __restrict__ gEtaA,
                const float* __restrict__ gZeta,
                const float* __restrict__ gShfA,    // (4,)
                const float* __restrict__ gShfZ,    // (8,)
                const int*   __restrict__ species,  // (M, A)
                float* __restrict__ out)            // (M, A, 384)
{
    const int m = blockIdx.y;
    const int tid = threadIdx.x;
    const int grp = tid >> 7;          // 0 or 1: which atom this half handles
    const int gtid = tid & 127;
    const int gwid = gtid >> 5;        // warp id within group (0..3)
    const int lane = tid & 31;
    const unsigned ltm = (1u << lane) - 1u;
    const int i = blockIdx.x * 2 + grp;   // atom index

    // molecule-shared
    __shared__ float sx[NA], sy[NA], sz[NA];
    __shared__ int   ssp[NA];
    __shared__ float shfr[NSHFR], shfa[NSHFA];
    __shared__ float cshfz[NSHFZ], sshfz[NSHFZ];
    __shared__ float s_etaR, s_etaA, s_zeta;
    // per-group
    __shared__ float dR[2][NA], qfcR[2][NA];
    __shared__ int   cntRspw[2][2][NS];
    __shared__ int   rstart[2][NS + 1];
    __shared__ float avx[2][NA], avy[2][NA], avz[2][NA], ad[2][NA], afc[2][NA];
    __shared__ int   asp[2][NA];
    __shared__ int   wcntA[2][2];
    __shared__ float f1s[2][CHUNK * 9];
    __shared__ float f2s[2][CHUNK * 5];
    __shared__ int   cntPw[2][GWARPS][NPAIRS_SP];
    __shared__ int   pstart[2][NPAIRS_SP + 1];
    __shared__ float radout[2][RAD_FEAT];

    // ---- phase 0: whole CTA loads molecule + params ----
    if (tid < NA) {
        const float* c = coords + ((size_t)m * NA + tid) * 3;
        sx[tid] = c[0];
        sy[tid] = c[1];
        sz[tid] = c[2];
        ssp[tid] = species[(size_t)m * NA + tid];
    }
    if (tid < NSHFR) shfr[tid] = gShfR[tid];
    if (tid < NSHFA) shfa[tid] = gShfA[tid];
    if (tid < NSHFZ) {
        float z = gShfZ[tid];
        cshfz[tid] = cosf(z);
        sshfz[tid] = sinf(z);
    }
    if (tid == 0) {
        s_etaR = gEtaR[0];
        s_etaA = gEtaA[0];
        s_zeta = gZeta[0];
    }
    if (tid < 2 * 2 * NS) ((int*)cntRspw)[tid] = 0;
    if (tid < 4) ((int*)wcntA)[tid] = 0;
    __syncthreads();   // last full-CTA barrier; groups decouple below

    const float cx = sx[i], cy = sy[i], cz = sz[i];
    const float etaR = s_etaR, etaA = s_etaA, zeta = s_zeta;
    const bool z32 = (zeta == 32.0f);

    // ---- phase 1: compaction (group warps 0,1 cover j = 0..47) ----
    {
        int j = gtid;
        float dx = 0.f, dy = 0.f, dz = 0.f, d = 1e9f;
        bool valid = (j < NA) && (j != i);
        int sp = 0;
        if (valid) {
            dx = sx[j] - cx;
            dy = sy[j] - cy;
            dz = sz[j] - cz;
            d = sqrtf(dx * dx + dy * dy + dz * dz);
            sp = ssp[j];
        }
        bool inR = valid && (d <= RCR_F);
        bool inA = valid && (d <= RCA_F);
        unsigned ballR = __ballot_sync(0xffffffffu, inR);
        unsigned ballA = __ballot_sync(0xffffffffu, inA);

        unsigned mspR = __match_any_sync(0xffffffffu, inR ? sp : (NS + lane)) & ballR;
        int rankR = __popc(mspR & ltm);
        if (inR && (lane == (__ffs(mspR) - 1)))
            cntRspw[grp][gwid][sp] = __popc(mspR);

        int rankA = __popc(ballA & ltm);
        if (gwid < 2 && lane == 0) wcntA[grp][gwid] = __popc(ballA);
        GBAR(grp);

        if (gtid <= NS) {
            int acc = 0;
            for (int s = 0; s < gtid; s++)
                acc += cntRspw[grp][0][s] + cntRspw[grp][1][s];
            rstart[grp][gtid] = acc;
        }
        GBAR(grp);

        if (inR) {
            int off = rstart[grp][sp] + rankR;
            if (gwid == 1) off += cntRspw[grp][0][sp];
            dR[grp][off] = d;
            qfcR[grp][off] = 0.25f * (0.5f * __cosf(d * (PI_F / RCR_F)) + 0.5f);
        }
        if (inA) {
            int off = rankA;
            if (gwid == 1) off += wcntA[grp][0];
            avx[grp][off] = dx; avy[grp][off] = dy; avz[grp][off] = dz;
            ad[grp][off] = d;
            afc[grp][off] = 0.5f * __cosf(d * (PI_F / RCA_F)) + 0.5f;
            asp[grp][off] = sp;
        }
    }
    GBAR(grp);
    const int nA = wcntA[grp][0] + wcntA[grp][1];

    // ---- phase 2: radial, feature-parallel over species buckets ----
    if (gtid < RAD_FEAT) {
        int sp = gtid >> 4;
        float sk = shfr[gtid & 15];
        float acc = 0.0f;
        int jb = rstart[grp][sp], je = rstart[grp][sp + 1];
        for (int j = jb; j < je; j++) {
            float t = dR[grp][j] - sk;
            acc += qfcR[grp][j] * __expf(-etaR * t * t);
        }
        radout[grp][gtid] = acc;
    }

    // ---- phase 3: angular pairs, chunked, pre-sorted by pidx ----
    const int npairs = nA * (nA - 1) / 2;
    float acc0 = 0.f, acc1 = 0.f, acc2 = 0.f;

    for (int base = 0; base < npairs; base += CHUNK) {
        int p = base + gtid;
        bool pvalid = (p < npairs);
        GBAR(grp);   // previous chunk's scan done before overwrite

        int a = 0, b = 0, pidx = NPAIRS_SP + lane;  // per-lane sentinel
        if (pvalid) {
            float fn = (float)nA;
            float tt = 2.0f * fn - 1.0f;
            a = (int)(0.5f * (tt - sqrtf(fmaxf(tt * tt - 8.0f * (float)p, 0.0f))));
            while (a > 0 && p < a * nA - (a * (a + 1)) / 2) a--;
            while (p >= (a + 1) * nA - ((a + 1) * (a + 2)) / 2) a++;
            b = p - (a * nA - (a * (a + 1)) / 2) + a + 1;
            pidx = triu_idx(asp[grp][a], asp[grp][b]);
        }

        unsigned msk = __match_any_sync(0xffffffffu, pidx);
        int rank = __popc(msk & ltm);
        #pragma unroll
        for (int k = 0; k < NPAIRS_SP; k++) {
            unsigned bk = __ballot_sync(0xffffffffu, pidx == k);
            if (lane == k) cntPw[grp][gwid][k] = __popc(bk);
        }
        GBAR(grp);

        // group warp 0: exclusive scan of cntPw over warps, then pstart
        if (gwid == 0) {
            int tot = 0;
            if (lane < NPAIRS_SP) {
                int acc = 0;
                #pragma unroll
                for (int w = 0; w < GWARPS; w++) {
                    int c = cntPw[grp][w][lane];
                    cntPw[grp][w][lane] = acc;
                    acc += c;
                }
                tot = acc;
            }
            int scan = tot;
            #pragma unroll
            for (int o = 1; o < 16; o <<= 1) {
                int v = __shfl_up_sync(0xffffffffu, scan, o);
                if (lane >= o) scan += v;
            }
            if (lane < NPAIRS_SP) pstart[grp][lane + 1] = scan;
            if (lane == 0) pstart[grp][0] = 0;
        }
        GBAR(grp);

        if (pvalid) {
            int slot = pstart[grp][pidx] + cntPw[grp][gwid][pidx] + rank;

            float d1 = ad[grp][a], d2 = ad[grp][b];
            float dot = avx[grp][a] * avx[grp][b] + avy[grp][a] * avy[grp][b]
                      + avz[grp][a] * avz[grp][b];
            float cosv = 0.95f * __fdividef(dot, fmaxf(d1, 1e-8f) * fmaxf(d2, 1e-8f));
            float sinv = sqrtf(fmaxf(1.0f - cosv * cosv, 0.0f));
            float dm = 0.5f * (d1 + d2);
            float fcj2 = 2.0f * afc[grp][a] * afc[grp][b];

            #pragma unroll
            for (int t = 0; t < NSHFZ; t++) {
                float c = cosv * cshfz[t] + sinv * sshfz[t];
                float bse = 0.5f * (1.0f + c);
                f1s[grp][slot * 9 + t] = pow_zeta(bse, zeta, z32) * fcj2;
            }
            #pragma unroll
            for (int s = 0; s < NSHFA; s++) {
                float dd = dm - shfa[s];
                f2s[grp][slot * 5 + s] = __expf(-etaA * dd * dd);
            }
        }
        GBAR(grp);

        // feature accumulation: group warp w scans bucket w, then 4+w, then 8,9
        {
            int s = (gtid >> 3) & 3, t = gtid & 7;
            int qb = pstart[grp][gwid], qe = pstart[grp][gwid + 1];
            for (int q = qb; q < qe; q++)
                acc0 += f1s[grp][q * 9 + t] * f2s[grp][q * 5 + s];
        }
        {
            int pf = 4 + gwid, s = (gtid >> 3) & 3, t = gtid & 7;
            int qb = pstart[grp][pf], qe = pstart[grp][pf + 1];
            for (int q = qb; q < qe; q++)
                acc1 += f1s[grp][q * 9 + t] * f2s[grp][q * 5 + s];
        }
        if (gtid < 64) {   // buckets 8,9 -> group warps 0,1
            int pf = 8 + (gtid >> 5), s = (gtid >> 3) & 3, t = gtid & 7;
            int qb = pstart[grp][pf], qe = pstart[grp][pf + 1];
            for (int q = qb; q < qe; q++)
                acc2 += f1s[grp][q * 9 + t] * f2s[grp][q * 5 + s];
        }
    }
    GBAR(grp);

    // ---- write out ----
    float* o = out + ((size_t)m * NA + i) * AEV_LEN;
    if (gtid < RAD_FEAT) o[gtid] = radout[grp][gtid];
    o[RAD_FEAT + gtid] = acc0;
    o[RAD_FEAT + 128 + gtid] = acc1;
    if (gtid < 64) o[RAD_FEAT + 256 + gtid] = acc2;
}

extern "C" void kernel_launch(void* const* d_in, const int* in_sizes, int n_in,
                              void* d_out, int out_size) {
    const float* coords = (const float*)d_in[0];
    const float* EtaR   = (const float*)d_in[1];
    const float* ShfR   = (const float*)d_in[2];
    const float* EtaA   = (const float*)d_in[3];
    const float* Zeta   = (const float*)d_in[4];
    const float* ShfA   = (const float*)d_in[5];
    const float* ShfZ   = (const float*)d_in[6];
    const int*   spec   = (const int*)d_in[7];
    float* out = (float*)d_out;

    int MA = in_sizes[7];
    int M = MA / NA;

    dim3 grid(NA / 2, M);
    aev_kernel<<<grid, NTHR>>>(coords, EtaR, ShfR, EtaA, Zeta, ShfA, ShfZ, spec, out);
}

// round 11
// speedup vs baseline: 1.3194x; 1.3194x over previous
#include <cuda_runtime.h>
#include <math.h>

#define NA 48
#define NS 4
#define NSHFR 16
#define NSHFA 4
#define NSHFZ 8
#define RAD_FEAT (NS * NSHFR)                     // 64
#define ANG_SUB (NSHFA * NSHFZ)                   // 32
#define NPAIRS_SP (NS * (NS + 1) / 2)             // 10
#define ANG_FEAT (NPAIRS_SP * ANG_SUB)            // 320
#define AEV_LEN (RAD_FEAT + ANG_FEAT)             // 384
#define RCR_F 5.2f
#define RCA_F 3.5f
#define PI_F 3.14159265358979323846f
#define NTHR 128
#define NWARP 4
#define CHUNK 128

__device__ __forceinline__ int triu_idx(int a, int b) {
    int lo = min(a, b), hi = max(a, b);
    return lo * NS - (lo * (lo - 1)) / 2 + (hi - lo);
}

__device__ __forceinline__ float pow_zeta(float x, float zeta, bool z32) {
    if (z32) {
        float y = x * x;  // ^2
        y = y * y;        // ^4
        y = y * y;        // ^8
        y = y * y;        // ^16
        return y * y;     // ^32
    }
    return __powf(x, zeta);
}

__global__ __launch_bounds__(NTHR, 12)
void aev_kernel(const float* __restrict__ coords,   // (M, A, 3)
                const float* __restrict__ gEtaR,
                const float* __restrict__ gShfR,    // (16,)
                const float* __restrict__ gEtaA,
                const float* __restrict__ gZeta,
                const float* __restrict__ gShfA,    // (4,)
                const float* __restrict__ gShfZ,    // (8,)
                const int*   __restrict__ species,  // (M, A)
                float* __restrict__ out)            // (M, A, 384)
{
    const int i = blockIdx.x;
    const int m = blockIdx.y;
    const int tid = threadIdx.x;
    const int lane = tid & 31;
    const int wid = tid >> 5;
    const unsigned ltm = (1u << lane) - 1u;

    __shared__ float sx[NA], sy[NA], sz[NA];
    __shared__ int   ssp[NA];
    __shared__ float shfr[NSHFR], shfa[NSHFA];
    __shared__ float cshfz[NSHFZ], sshfz[NSHFZ];
    __shared__ float s_etaR, s_etaA, s_zeta;
    // radial list, sorted by species
    __shared__ float dR[NA], qfcR[NA];
    __shared__ int   cntRspw[2][NS];
    __shared__ int   rstart[NS + 1];
    // angular list (ballot order)
    __shared__ float avx[NA], avy[NA], avz[NA], ad[NA], afc[NA];
    __shared__ int   asp[NA];
    __shared__ int   wcntA[2];
    // per-chunk pair data (stored pre-sorted by pidx)
    __shared__ float f1s[CHUNK * 9];           // padded stride 9
    __shared__ float f2s[CHUNK * 5];           // padded stride 5
    __shared__ int   cntPw[NWARP][NPAIRS_SP];  // becomes exclusive warp-prefix
    __shared__ int   pstart[NPAIRS_SP + 1];
    __shared__ float radout[RAD_FEAT];

    // ---- phase 0: load ----
    if (tid < NA) {
        const float* c = coords + ((size_t)m * NA + tid) * 3;
        sx[tid] = c[0];
        sy[tid] = c[1];
        sz[tid] = c[2];
        ssp[tid] = species[(size_t)m * NA + tid];
    }
    if (tid < NSHFR) shfr[tid] = gShfR[tid];
    if (tid < NSHFA) shfa[tid] = gShfA[tid];
    if (tid < NSHFZ) {
        float z = gShfZ[tid];
        cshfz[tid] = cosf(z);
        sshfz[tid] = sinf(z);
    }
    if (tid == 0) {
        s_etaR = gEtaR[0];
        s_etaA = gEtaA[0];
        s_zeta = gZeta[0];
    }
    if (tid < 2 * NS) ((int*)cntRspw)[tid] = 0;
    if (tid < 2) wcntA[tid] = 0;
    __syncthreads();

    const float cx = sx[i], cy = sy[i], cz = sz[i];
    const float etaR = s_etaR, etaA = s_etaA, zeta = s_zeta;
    const bool z32 = (zeta == 32.0f);

    // ---- phase 1: deterministic compaction (warps 0,1 cover j = 0..47) ----
    if (wid < 2) {
        int j = tid;
        float dx = 0.f, dy = 0.f, dz = 0.f, d = 1e9f;
        bool valid = (j < NA) && (j != i);
        int sp = 0;
        if (valid) {
            dx = sx[j] - cx;
            dy = sy[j] - cy;
            dz = sz[j] - cz;
            d = sqrtf(dx * dx + dy * dy + dz * dz);
            sp = ssp[j];
        }
        bool inR = valid && (d <= RCR_F);
        bool inA = valid && (d <= RCA_F);
        unsigned ballR = __ballot_sync(0xffffffffu, inR);
        unsigned ballA = __ballot_sync(0xffffffffu, inA);

        unsigned mspR = __match_any_sync(0xffffffffu, inR ? sp : (NS + lane)) & ballR;
        int rankR = __popc(mspR & ltm);
        if (inR && (lane == (__ffs(mspR) - 1)))
            cntRspw[wid][sp] = __popc(mspR);

        int rankA = __popc(ballA & ltm);
        if (lane == 0) wcntA[wid] = __popc(ballA);
        __syncthreads();

        if (tid <= NS) {
            int acc = 0;
            for (int s = 0; s < tid; s++)
                acc += cntRspw[0][s] + cntRspw[1][s];
            rstart[tid] = acc;
        }
        __syncthreads();

        if (inR) {
            int off = rstart[sp] + rankR;
            if (wid == 1) off += cntRspw[0][sp];
            dR[off] = d;
            qfcR[off] = 0.25f * (0.5f * __cosf(d * (PI_F / RCR_F)) + 0.5f);
        }
        if (inA) {
            int off = rankA;
            if (wid == 1) off += wcntA[0];
            avx[off] = dx; avy[off] = dy; avz[off] = dz;
            ad[off] = d;
            afc[off] = 0.5f * __cosf(d * (PI_F / RCA_F)) + 0.5f;
            asp[off] = sp;
        }
    } else {
        __syncthreads();
        __syncthreads();
    }
    __syncthreads();
    const int nA = wcntA[0] + wcntA[1];

    // ---- phase 2: radial, feature-parallel over species buckets ----
    if (tid < RAD_FEAT) {
        int sp = tid >> 4;
        float sk = shfr[tid & 15];
        float acc = 0.0f;
        int jb = rstart[sp], je = rstart[sp + 1];
        for (int j = jb; j < je; j++) {
            float t = dR[j] - sk;
            acc += qfcR[j] * __expf(-etaR * t * t);
        }
        radout[tid] = acc;
    }

    // ---- phase 3: angular pairs, chunked, pre-sorted by pidx ----
    const int npairs = nA * (nA - 1) / 2;
    float acc0 = 0.f, acc1 = 0.f, acc2 = 0.f;

    for (int base = 0; base < npairs; base += CHUNK) {
        int p = base + tid;
        bool pvalid = (p < npairs);
        __syncthreads();   // previous chunk's scan complete before overwriting

        int a = 0, b = 0, pidx = NPAIRS_SP + lane;  // sentinel distinct per lane
        if (pvalid) {
            // closed-form decode p -> (a,b), a < b, with rounding fix-up
            float fn = (float)nA;
            float tt = 2.0f * fn - 1.0f;
            a = (int)(0.5f * (tt - sqrtf(fmaxf(tt * tt - 8.0f * (float)p, 0.0f))));
            while (a > 0 && p < a * nA - (a * (a + 1)) / 2) a--;
            while (p >= (a + 1) * nA - ((a + 1) * (a + 2)) / 2) a++;
            b = p - (a * nA - (a * (a + 1)) / 2) + a + 1;
            pidx = triu_idx(asp[a], asp[b]);
        }

        // per-warp per-bucket histogram via ballots; rank via match
        unsigned msk = __match_any_sync(0xffffffffu, pidx);
        int rank = __popc(msk & ltm);
        #pragma unroll
        for (int k = 0; k < NPAIRS_SP; k++) {
            unsigned bk = __ballot_sync(0xffffffffu, pidx == k);
            if (lane == k) cntPw[wid][k] = __popc(bk);
        }
        __syncthreads();

        // warp 0: exclusive scan of cntPw over warps per bucket, then pstart
        if (wid == 0) {
            int tot = 0;
            if (lane < NPAIRS_SP) {
                int acc = 0;
                #pragma unroll
                for (int w = 0; w < NWARP; w++) {
                    int c = cntPw[w][lane];
                    cntPw[w][lane] = acc;
                    acc += c;
                }
                tot = acc;
            }
            int scan = tot;
            #pragma unroll
            for (int o = 1; o < 16; o <<= 1) {
                int v = __shfl_up_sync(0xffffffffu, scan, o);
                if (lane >= o) scan += v;
            }
            if (lane < NPAIRS_SP) pstart[lane + 1] = scan;
            if (lane == 0) pstart[0] = 0;
        }
        __syncthreads();

        if (pvalid) {
            int slot = pstart[pidx] + cntPw[wid][pidx] + rank;

            float d1 = ad[a], d2 = ad[b];
            float dot = avx[a] * avx[b] + avy[a] * avy[b] + avz[a] * avz[b];
            float cosv = 0.95f * __fdividef(dot, fmaxf(d1, 1e-8f) * fmaxf(d2, 1e-8f));
            float sinv = sqrtf(fmaxf(1.0f - cosv * cosv, 0.0f));
            float dm = 0.5f * (d1 + d2);
            float fcj2 = 2.0f * afc[a] * afc[b];

            #pragma unroll
            for (int t = 0; t < NSHFZ; t++) {
                float c = cosv * cshfz[t] + sinv * sshfz[t];
                float bse = 0.5f * (1.0f + c);
                f1s[slot * 9 + t] = pow_zeta(bse, zeta, z32) * fcj2;
            }
            #pragma unroll
            for (int s = 0; s < NSHFA; s++) {
                float dd = dm - shfa[s];
                f2s[slot * 5 + s] = __expf(-etaA * dd * dd);
            }
        }
        __syncthreads();

        // feature accumulation: warp w scans bucket w, then 4+w; warps 0,1: 8,9
        {
            int s = (tid >> 3) & 3, t = tid & 7;
            int qb = pstart[wid], qe = pstart[wid + 1];
            for (int q = qb; q < qe; q++)
                acc0 += f1s[q * 9 + t] * f2s[q * 5 + s];
        }
        {
            int pf = 4 + wid, s = (tid >> 3) & 3, t = tid & 7;
            int qb = pstart[pf], qe = pstart[pf + 1];
            for (int q = qb; q < qe; q++)
                acc1 += f1s[q * 9 + t] * f2s[q * 5 + s];
        }
        if (tid < 64) {   // buckets 8,9 -> warps 0,1
            int pf = 8 + (tid >> 5), s = (tid >> 3) & 3, t = tid & 7;
            int qb = pstart[pf], qe = pstart[pf + 1];
            for (int q = qb; q < qe; q++)
                acc2 += f1s[q * 9 + t] * f2s[q * 5 + s];
        }
    }
    __syncthreads();

    // ---- write out ----
    float* o = out + ((size_t)m * NA + i) * AEV_LEN;
    if (tid < RAD_FEAT) o[tid] = radout[tid];
    o[RAD_FEAT + tid] = acc0;
    o[RAD_FEAT + 128 + tid] = acc1;
    if (tid < 64) o[RAD_FEAT + 256 + tid] = acc2;
}

extern "C" void kernel_launch(void* const* d_in, const int* in_sizes, int n_in,
                              void* d_out, int out_size) {
    const float* coords = (const float*)d_in[0];
    const float* EtaR   = (const float*)d_in[1];
    const float* ShfR   = (const float*)d_in[2];
    const float* EtaA   = (const float*)d_in[3];
    const float* Zeta   = (const float*)d_in[4];
    const float* ShfA   = (const float*)d_in[5];
    const float* ShfZ   = (const float*)d_in[6];
    const int*   spec   = (const int*)d_in[7];
    float* out = (float*)d_out;

    int MA = in_sizes[7];
    int M = MA / NA;

    dim3 grid(NA, M);
    aev_kernel<<<grid, NTHR>>>(coords, EtaR, ShfR, EtaA, Zeta, ShfA, ShfZ, spec, out);
}